// round 4
// baseline (speedup 1.0000x reference)
#include <cuda_runtime.h>
#include <cuda_bf16.h>
#include <math.h>
#include <stdint.h>

#define Bb    8
#define Cc    256
#define HW    4096
#define PER_B (Cc * HW)          // 2^20
#define EPSF  1e-12f

// ---------------- device scratch ----------------
__device__ float g_Q[7][Bb * PER_B];   // unnormalized Krylov vectors, slots 1..7 (slot 0 = input v)
__device__ float g_w[Bb * PER_B];      // GEMM output (scaled by inv_k)
__device__ __nv_bfloat16 g_Rhi[Bb * PER_B];  // replicator out (UNNORMALIZED), transposed [b][p][c], hi
__device__ __nv_bfloat16 g_Rlo[Bb * PER_B];  // lo residual
__device__ __nv_bfloat16 g_Whi[Cc * Cc];
__device__ __nv_bfloat16 g_Wlo[Cc * Cc];
__device__ float g_dpart[8][Bb][128];  // dot partials [j][b][p-block]
__device__ float g_npart[Bb][128];     // norm partials
__device__ float g_H[Bb][8][8];
__device__ float g_inv[8][Bb];
__device__ float g_hcoef[8][Bb];
__device__ float g_vnorm[Bb];
__device__ float g_cf[Bb][8];

// ---------------- helpers ----------------
__device__ __forceinline__ float blockReduce256(float val) {
    __shared__ float sh[256];
    int t = threadIdx.x;
    sh[t] = val; __syncthreads();
    #pragma unroll
    for (int s = 128; s > 0; s >>= 1) {
        if (t < s) sh[t] += sh[t + s];
        __syncthreads();
    }
    float r = sh[0];
    __syncthreads();
    return r;
}

// ---------------- W split to bf16 hi/lo ----------------
__global__ void __launch_bounds__(256) k_splitW(const float* __restrict__ Wm) {
    int i = blockIdx.x * 256 + threadIdx.x;
    float x = Wm[i];
    __nv_bfloat16 h = __float2bfloat16(x);
    g_Whi[i] = h;
    g_Wlo[i] = __float2bfloat16(x - __bfloat162float(h));
}

// ---------------- shared: write transposed bf16-split R from x[32] registers ----------------
static __device__ __forceinline__ void write_R(const float* xv, const float* sv, float S,
                                               int b, int p, int cg) {
    uint32_t phi[16], plo[16];
    #pragma unroll
    for (int i = 0; i < 16; i++) {
        float x0 = sv[2*i]   * (xv[2*i]   - S);
        float x1 = sv[2*i+1] * (xv[2*i+1] - S);
        __nv_bfloat16 h0 = __float2bfloat16(x0);
        __nv_bfloat16 h1 = __float2bfloat16(x1);
        __nv_bfloat16 l0 = __float2bfloat16(x0 - __bfloat162float(h0));
        __nv_bfloat16 l1 = __float2bfloat16(x1 - __bfloat162float(h1));
        phi[i] = (uint32_t)__bfloat16_as_ushort(h0) | ((uint32_t)__bfloat16_as_ushort(h1) << 16);
        plo[i] = (uint32_t)__bfloat16_as_ushort(l0) | ((uint32_t)__bfloat16_as_ushort(l1) << 16);
    }
    size_t ob = ((size_t)b * HW + p) * 256 + cg * 32;
    uint4* dh = (uint4*)(g_Rhi + ob);
    uint4* dl = (uint4*)(g_Rlo + ob);
    #pragma unroll
    for (int i = 0; i < 4; i++) {
        dh[i] = make_uint4(phi[4*i], phi[4*i+1], phi[4*i+2], phi[4*i+3]);
        dl[i] = make_uint4(plo[4*i], plo[4*i+1], plo[4*i+2], plo[4*i+3]);
    }
}

// ---------------- step-0 replicator: R(v) unnormalized + ||v||^2 partials ----------------
__global__ void __launch_bounds__(256) k_repl0(const float* __restrict__ s0,
                                               const float* __restrict__ v) {
    int b  = blockIdx.y;
    int p  = blockIdx.x * 32 + (threadIdx.x & 31);
    int cg = threadIdx.x >> 5;
    size_t base = (size_t)b * PER_B + p;

    float sv[32], xv[32];
    float part = 0.f, nacc = 0.f;
    #pragma unroll
    for (int i = 0; i < 32; i++) {
        size_t off = base + (size_t)(cg * 32 + i) * HW;
        sv[i] = s0[off]; xv[i] = v[off];
        part += sv[i] * xv[i];
        nacc += xv[i] * xv[i];
    }
    __shared__ float red[8][32];
    __shared__ float Ssh[32];
    red[cg][threadIdx.x & 31] = part;
    __syncthreads();
    if (cg == 0) {
        float s = 0.f;
        #pragma unroll
        for (int g = 0; g < 8; g++) s += red[g][threadIdx.x];
        Ssh[threadIdx.x] = s;
    }
    __syncthreads();
    float S = Ssh[threadIdx.x & 31];

    float nr = blockReduce256(nacc);
    if (threadIdx.x == 0) g_npart[b][blockIdx.x] = nr;

    write_R(xv, sv, S, b, p, cg);
}

// ---------------- fused update + replicator + norm (k = 0..6) ----------------
// x = w - sum_j hcoef_j * Q_j ; Q_{k+1} = x (fp32) ; R = s0*(x - s0.x sums) unnormalized
__global__ void __launch_bounds__(256) k_upd_repl(const float* __restrict__ s0,
                                                  const float* __restrict__ v, int k) {
    int b  = blockIdx.y;
    int p  = blockIdx.x * 32 + (threadIdx.x & 31);
    int cg = threadIdx.x >> 5;
    size_t base = (size_t)b * PER_B + p;

    float xv[32];
    #pragma unroll
    for (int i = 0; i < 32; i++)
        xv[i] = g_w[base + (size_t)(cg * 32 + i) * HW];

    for (int j = 0; j <= k; j++) {
        const float* __restrict__ Qj = (j == 0) ? v : g_Q[j - 1];
        float cf = g_hcoef[j][b];
        #pragma unroll
        for (int i = 0; i < 32; i++)
            xv[i] -= cf * Qj[base + (size_t)(cg * 32 + i) * HW];
    }

    // write Q_{k+1} and gather norm + s0 dot
    float* __restrict__ qn = g_Q[k];
    float sv[32];
    float nacc = 0.f, part = 0.f;
    #pragma unroll
    for (int i = 0; i < 32; i++) {
        size_t off = base + (size_t)(cg * 32 + i) * HW;
        qn[off] = xv[i];
        nacc += xv[i] * xv[i];
        sv[i] = s0[off];
        part += sv[i] * xv[i];
    }

    __shared__ float red[8][32];
    __shared__ float Ssh[32];
    red[cg][threadIdx.x & 31] = part;
    __syncthreads();
    if (cg == 0) {
        float s = 0.f;
        #pragma unroll
        for (int g = 0; g < 8; g++) s += red[g][threadIdx.x];
        Ssh[threadIdx.x] = s;
    }
    __syncthreads();
    float S = Ssh[threadIdx.x & 31];

    float nr = blockReduce256(nacc);
    if (threadIdx.x == 0) g_npart[b][blockIdx.x] = nr;

    write_R(xv, sv, S, b, p, cg);
}

// ---------------- norm finalize (k=-1: vnorm; else H[k+1][k], inv[k+1]) ----------------
__global__ void __launch_bounds__(128) k_norm_fin(int k) {
    int b = blockIdx.x, t = threadIdx.x;
    __shared__ float sh[128];
    sh[t] = g_npart[b][t]; __syncthreads();
    #pragma unroll
    for (int s = 64; s > 0; s >>= 1) { if (t < s) sh[t] += sh[t + s]; __syncthreads(); }
    if (t == 0) {
        if (k < 0) {
            float vn = sqrtf(sh[0]);
            g_vnorm[b] = vn; g_inv[0][b] = 1.f / vn;
        } else {
            float hn = sqrtf(sh[0]);
            g_H[b][k + 1][k] = hn;
            g_inv[k + 1][b]  = 1.f / (hn + EPSF);
        }
    }
}

// ---------------- dots finalize ----------------
__global__ void __launch_bounds__(128) k_dots_fin(int k) {
    int j = blockIdx.x, b = blockIdx.y, t = threadIdx.x;
    __shared__ float sh[128];
    sh[t] = g_dpart[j][b][t]; __syncthreads();
    #pragma unroll
    for (int s = 64; s > 0; s >>= 1) { if (t < s) sh[t] += sh[t + s]; __syncthreads(); }
    if (t == 0) {
        float h = sh[0] * g_inv[j][b];
        g_H[b][j][k]  = h;
        g_hcoef[j][b] = h * g_inv[j][b];
    }
}

// ---------------- fused GEMM + dots ----------------
// w[b,o,p] = inv_k * sum_c W[o,c]*R[b,c,p] (3-term bf16 split), then dot partials vs Q_j.
// CTA: M=256 (all o), N=32 (p). 8 warps, warp tile 32(m) x 32(n). K chunks of 64.
static __device__ __forceinline__ void ldtileA(char* sm, uint32_t off,
                                               const __nv_bfloat16* src, int kc, int tid) {
    #pragma unroll
    for (int i = 0; i < 8; i++) {
        int x = tid + (i << 8);
        int row = x >> 3;
        int cb  = (x & 7) << 4;
        uint4 val = *(const uint4*)((const char*)(src + (size_t)row * 256 + kc) + cb);
        uint32_t bo = (uint32_t)(row * 128 + (cb ^ ((row & 7) << 4)));
        *(uint4*)(sm + off + bo) = val;
    }
}
static __device__ __forceinline__ void ldtileB(char* sm, uint32_t off,
                                               const __nv_bfloat16* src, int kc, int tid) {
    int row = tid >> 3;
    int cb  = (tid & 7) << 4;
    uint4 val = *(const uint4*)((const char*)(src + (size_t)row * 256 + kc) + cb);
    uint32_t bo = (uint32_t)(row * 128 + (cb ^ ((row & 7) << 4)));
    *(uint4*)(sm + off + bo) = val;
}

static __device__ __forceinline__ void mma_bf16(float* c, const uint32_t* a, const uint32_t* b) {
    asm volatile("mma.sync.aligned.m16n8k16.row.col.f32.bf16.bf16.f32 "
        "{%0,%1,%2,%3}, {%4,%5,%6,%7}, {%8,%9}, {%0,%1,%2,%3};"
        : "+f"(c[0]), "+f"(c[1]), "+f"(c[2]), "+f"(c[3])
        : "r"(a[0]), "r"(a[1]), "r"(a[2]), "r"(a[3]), "r"(b[0]), "r"(b[1]));
}

__global__ void __launch_bounds__(256) k_gemm_fused(const float* __restrict__ v,
                                                    int kstep, int write_w) {
    extern __shared__ __align__(16) char smem[];
    const int tid  = threadIdx.x;
    const int wid  = tid >> 5;
    const int lane = tid & 31;
    const int g    = lane >> 2;
    const int q    = lane & 3;
    const int p0   = blockIdx.x * 32;
    const int b    = blockIdx.y;

    const uint32_t OFF_AH = 0, OFF_AL = 32768, OFF_BH = 65536, OFF_BL = 69632;
    const uint32_t swz = (uint32_t)(g << 4);

    const __nv_bfloat16* Bhi = g_Rhi + ((size_t)b * HW + p0) * 256;
    const __nv_bfloat16* Blo = g_Rlo + ((size_t)b * HW + p0) * 256;

    float acc[2][4][4];
    #pragma unroll
    for (int i = 0; i < 2; i++)
        #pragma unroll
        for (int j = 0; j < 4; j++)
            #pragma unroll
            for (int e = 0; e < 4; e++) acc[i][j][e] = 0.f;

    for (int kc = 0; kc < 256; kc += 64) {
        ldtileA(smem, OFF_AH, g_Whi, kc, tid);
        ldtileA(smem, OFF_AL, g_Wlo, kc, tid);
        ldtileB(smem, OFF_BH, Bhi, kc, tid);
        ldtileB(smem, OFF_BL, Blo, kc, tid);
        __syncthreads();

        #pragma unroll
        for (int kf = 0; kf < 4; kf++) {
            const uint32_t cb0 = (uint32_t)(kf * 32 + q * 4);
            const uint32_t c0 = cb0 ^ swz, c1 = (cb0 + 16) ^ swz;
            uint32_t ah[2][4], ao[2][4], bt[4][2];
            #pragma unroll
            for (int mf = 0; mf < 2; mf++) {
                uint32_t r0 = (uint32_t)(wid * 32 + mf * 16 + g) * 128;
                uint32_t r1 = r0 + 1024;
                ah[mf][0] = *(const uint32_t*)(smem + OFF_AH + r0 + c0);
                ah[mf][1] = *(const uint32_t*)(smem + OFF_AH + r1 + c0);
                ah[mf][2] = *(const uint32_t*)(smem + OFF_AH + r0 + c1);
                ah[mf][3] = *(const uint32_t*)(smem + OFF_AH + r1 + c1);
            }
            #pragma unroll
            for (int nf = 0; nf < 4; nf++) {
                uint32_t nr = (uint32_t)(nf * 8 + g) * 128;
                bt[nf][0] = *(const uint32_t*)(smem + OFF_BH + nr + c0);
                bt[nf][1] = *(const uint32_t*)(smem + OFF_BH + nr + c1);
            }
            #pragma unroll
            for (int mf = 0; mf < 2; mf++)
                #pragma unroll
                for (int nf = 0; nf < 4; nf++) mma_bf16(acc[mf][nf], ah[mf], bt[nf]);
            #pragma unroll
            for (int mf = 0; mf < 2; mf++) {
                uint32_t r0 = (uint32_t)(wid * 32 + mf * 16 + g) * 128;
                uint32_t r1 = r0 + 1024;
                ao[mf][0] = *(const uint32_t*)(smem + OFF_AL + r0 + c0);
                ao[mf][1] = *(const uint32_t*)(smem + OFF_AL + r1 + c0);
                ao[mf][2] = *(const uint32_t*)(smem + OFF_AL + r0 + c1);
                ao[mf][3] = *(const uint32_t*)(smem + OFF_AL + r1 + c1);
            }
            #pragma unroll
            for (int mf = 0; mf < 2; mf++)
                #pragma unroll
                for (int nf = 0; nf < 4; nf++) mma_bf16(acc[mf][nf], ao[mf], bt[nf]);
            #pragma unroll
            for (int nf = 0; nf < 4; nf++) {
                uint32_t nr = (uint32_t)(nf * 8 + g) * 128;
                bt[nf][0] = *(const uint32_t*)(smem + OFF_BL + nr + c0);
                bt[nf][1] = *(const uint32_t*)(smem + OFF_BL + nr + c1);
            }
            #pragma unroll
            for (int mf = 0; mf < 2; mf++)
                #pragma unroll
                for (int nf = 0; nf < 4; nf++) mma_bf16(acc[mf][nf], ah[mf], bt[nf]);
        }
        __syncthreads();
    }

    // scale by inv_k (deferred normalization of q_k)
    const float inv = g_inv[kstep][b];
    #pragma unroll
    for (int mf = 0; mf < 2; mf++)
        #pragma unroll
        for (int nf = 0; nf < 4; nf++)
            #pragma unroll
            for (int e = 0; e < 4; e++) acc[mf][nf][e] *= inv;

    if (write_w) {
        float* dst = g_w + (size_t)b * PER_B + p0;
        #pragma unroll
        for (int mf = 0; mf < 2; mf++) {
            int m = wid * 32 + mf * 16 + g;
            #pragma unroll
            for (int nf = 0; nf < 4; nf++) {
                int pp = nf * 8 + q * 2;
                *(float2*)(dst + (size_t)m * HW + pp)       = make_float2(acc[mf][nf][0], acc[mf][nf][1]);
                *(float2*)(dst + (size_t)(m + 8) * HW + pp) = make_float2(acc[mf][nf][2], acc[mf][nf][3]);
            }
        }
    }

    // fused dots: partial <Q_j, w> over this CTA's (all c) x (32 p) slice
    float* sh = (float*)smem;
    for (int j = 0; j <= kstep; j++) {
        const float* Qb = ((j == 0) ? v : g_Q[j - 1]) + (size_t)b * PER_B + p0;
        float d = 0.f;
        #pragma unroll
        for (int mf = 0; mf < 2; mf++) {
            int m = wid * 32 + mf * 16 + g;
            #pragma unroll
            for (int nf = 0; nf < 4; nf++) {
                int pp = nf * 8 + q * 2;
                float2 a0 = *(const float2*)(Qb + (size_t)m * HW + pp);
                float2 a1 = *(const float2*)(Qb + (size_t)(m + 8) * HW + pp);
                d += acc[mf][nf][0] * a0.x + acc[mf][nf][1] * a0.y
                   + acc[mf][nf][2] * a1.x + acc[mf][nf][3] * a1.y;
            }
        }
        sh[tid] = d; __syncthreads();
        #pragma unroll
        for (int s = 128; s > 0; s >>= 1) { if (tid < s) sh[tid] += sh[tid + s]; __syncthreads(); }
        if (tid == 0) g_dpart[j][b][blockIdx.x] = sh[0];
        __syncthreads();
    }
}

// ---------------- expm of 9x9 (scaling-squaring + Taylor, fp64) ----------------
__global__ void k_expm() {
    const int b = blockIdx.x;
    const int t = threadIdx.x;
    __shared__ double A[81], M[81], P[81], Pn[81];
    __shared__ int ssc;

    if (t < 81) {
        int i = t / 9, j = t % 9;
        double e = 0.0;
        if (i < 8 && j < 8) e = (double)g_H[b][i][j];
        if (i == 0 && j == 8) e = 1.0;
        A[t] = e;
    }
    __syncthreads();
    if (t == 0) {
        double nrm = 0.0;
        for (int i = 0; i < 9; i++) {
            double rs = 0.0;
            for (int j = 0; j < 9; j++) rs += fabs(A[i * 9 + j]);
            if (rs > nrm) nrm = rs;
        }
        int s = 0;
        while (nrm > 0.5 && s < 60) { nrm *= 0.5; s++; }
        ssc = s;
    }
    __syncthreads();
    const int s = ssc;
    if (t < 81) {
        A[t] = ldexp(A[t], -s);
        M[t] = ((t % 10 == 0) ? 1.0 : 0.0) + A[t];
        P[t] = A[t];
    }
    __syncthreads();
    for (int it = 2; it <= 22; it++) {
        if (t < 81) {
            int i = t / 9, j = t % 9;
            double acc = 0.0;
            #pragma unroll
            for (int kk = 0; kk < 9; kk++) acc += P[i * 9 + kk] * A[kk * 9 + j];
            Pn[t] = acc / (double)it;
        }
        __syncthreads();
        if (t < 81) { P[t] = Pn[t]; M[t] += P[t]; }
        __syncthreads();
    }
    for (int qq = 0; qq < s; qq++) {
        if (t < 81) {
            int i = t / 9, j = t % 9;
            double acc = 0.0;
            #pragma unroll
            for (int kk = 0; kk < 9; kk++) acc += M[i * 9 + kk] * M[kk * 9 + j];
            Pn[t] = acc;
        }
        __syncthreads();
        if (t < 81) M[t] = Pn[t];
        __syncthreads();
    }
    if (t < 8) {
        double coord = M[t * 9 + 8];
        g_cf[b][t] = (float)(coord * (double)g_vnorm[b] * (double)g_inv[t][b]);
    }
}

// ---------------- final combine ----------------
__global__ void __launch_bounds__(256) k_combine(const float* __restrict__ v,
                                                 float* __restrict__ out) {
    int b = blockIdx.y, blk = blockIdx.x, t = threadIdx.x;
    size_t base = (size_t)b * PER_B + (size_t)blk * 2048 + t;
    const float* qs[8];
    float cf[8];
    #pragma unroll
    for (int j = 0; j < 8; j++) { qs[j] = (j == 0) ? v : g_Q[j - 1]; cf[j] = g_cf[b][j]; }
    #pragma unroll
    for (int e = 0; e < 8; e++) {
        size_t idx = base + e * 256;
        float x = 0.f;
        #pragma unroll
        for (int j = 0; j < 8; j++) x += cf[j] * qs[j][idx];
        out[idx] = x;
    }
}

// ---------------- driver ----------------
extern "C" void kernel_launch(void* const* d_in, const int* in_sizes, int n_in,
                              void* d_out, int out_size) {
    const float* s0 = (const float*)d_in[0];
    const float* v  = (const float*)d_in[1];
    const float* Wm = (const float*)d_in[2];
    float* out = (float*)d_out;

    const int GEMM_SMEM = 73728;
    cudaFuncSetAttribute(k_gemm_fused, cudaFuncAttributeMaxDynamicSharedMemorySize, GEMM_SMEM);

    dim3 gP(HW / 32, Bb);   // 128 p-blocks x 8 batches
    dim3 gEl(512, Bb);

    k_splitW<<<Cc * Cc / 256, 256>>>(Wm);
    k_repl0<<<gP, 256>>>(s0, v);
    k_norm_fin<<<Bb, 128>>>(-1);

    for (int k = 0; k < 8; k++) {
        k_gemm_fused<<<gP, 256, GEMM_SMEM>>>(v, k, (k < 7) ? 1 : 0);
        k_dots_fin<<<dim3(k + 1, Bb), 128>>>(k);
        if (k < 7) {
            k_upd_repl<<<gP, 256>>>(s0, v, k);
            k_norm_fin<<<Bb, 128>>>(k);
        }
    }

    k_expm<<<Bb, 128>>>();
    k_combine<<<gEl, 256>>>(v, out);
}

// round 5
// speedup vs baseline: 1.2252x; 1.2252x over previous
#include <cuda_runtime.h>
#include <cuda_bf16.h>
#include <math.h>
#include <stdint.h>

#define Bb    8
#define Cc    256
#define HW    4096
#define PER_B (Cc * HW)          // 2^20
#define EPSF  1e-12f

// ---------------- device scratch ----------------
__device__ float g_Q[7][Bb * PER_B];   // unnormalized Krylov vectors, slots 1..7 (slot 0 = input v)
__device__ float g_w[Bb * PER_B];      // GEMM output (scaled by inv_k)
__device__ __nv_bfloat16 g_Rhi[Bb * PER_B];  // replicator out (UNNORMALIZED), transposed [b][p][c], hi
__device__ __nv_bfloat16 g_Rlo[Bb * PER_B];  // lo residual
__device__ __nv_bfloat16 g_Whi[Cc * Cc];
__device__ __nv_bfloat16 g_Wlo[Cc * Cc];
__device__ float g_dpart[8][Bb][64];   // dot partials [j][b][mt*32+pblock]
__device__ float g_npart[Bb][128];     // norm partials
__device__ float g_H[Bb][8][8];
__device__ float g_inv[8][Bb];
__device__ float g_hcoef[8][Bb];
__device__ float g_vnorm[Bb];
__device__ float g_cf[Bb][8];

// ---------------- PTX helpers ----------------
static __device__ __forceinline__ uint32_t smem_u32(const void* p) {
    uint32_t a;
    asm("{ .reg .u64 t; cvta.to.shared.u64 t, %1; cvt.u32.u64 %0, t; }" : "=r"(a) : "l"(p));
    return a;
}
#define CP16(dst, src) \
    asm volatile("cp.async.cg.shared.global [%0], [%1], 16;" :: "r"(dst), "l"(src))
#define CP_COMMIT() asm volatile("cp.async.commit_group;" ::: "memory")
#define CP_WAIT1()  asm volatile("cp.async.wait_group 1;" ::: "memory")
#define CP_WAIT0()  asm volatile("cp.async.wait_group 0;" ::: "memory")
#define LDSM4(r0, r1, r2, r3, addr) \
    asm volatile("ldmatrix.sync.aligned.m8n8.x4.shared.b16 {%0,%1,%2,%3}, [%4];" \
        : "=r"(r0), "=r"(r1), "=r"(r2), "=r"(r3) : "r"(addr))

static __device__ __forceinline__ void mma_bf16(float* c, const uint32_t* a, const uint32_t* b) {
    asm volatile("mma.sync.aligned.m16n8k16.row.col.f32.bf16.bf16.f32 "
        "{%0,%1,%2,%3}, {%4,%5,%6,%7}, {%8,%9}, {%0,%1,%2,%3};"
        : "+f"(c[0]), "+f"(c[1]), "+f"(c[2]), "+f"(c[3])
        : "r"(a[0]), "r"(a[1]), "r"(a[2]), "r"(a[3]), "r"(b[0]), "r"(b[1]));
}

// ---------------- helpers ----------------
__device__ __forceinline__ float blockReduce256(float val) {
    __shared__ float sh[256];
    int t = threadIdx.x;
    sh[t] = val; __syncthreads();
    #pragma unroll
    for (int s = 128; s > 0; s >>= 1) {
        if (t < s) sh[t] += sh[t + s];
        __syncthreads();
    }
    float r = sh[0];
    __syncthreads();
    return r;
}

// ---------------- W split to bf16 hi/lo ----------------
__global__ void __launch_bounds__(256) k_splitW(const float* __restrict__ Wm) {
    int i = blockIdx.x * 256 + threadIdx.x;
    float x = Wm[i];
    __nv_bfloat16 h = __float2bfloat16(x);
    g_Whi[i] = h;
    g_Wlo[i] = __float2bfloat16(x - __bfloat162float(h));
}

// ---------------- shared: write transposed bf16-split R from x[32] registers ----------------
static __device__ __forceinline__ void write_R(const float* xv, const float* sv, float S,
                                               int b, int p, int cg) {
    uint32_t phi[16], plo[16];
    #pragma unroll
    for (int i = 0; i < 16; i++) {
        float x0 = sv[2*i]   * (xv[2*i]   - S);
        float x1 = sv[2*i+1] * (xv[2*i+1] - S);
        __nv_bfloat16 h0 = __float2bfloat16(x0);
        __nv_bfloat16 h1 = __float2bfloat16(x1);
        __nv_bfloat16 l0 = __float2bfloat16(x0 - __bfloat162float(h0));
        __nv_bfloat16 l1 = __float2bfloat16(x1 - __bfloat162float(h1));
        phi[i] = (uint32_t)__bfloat16_as_ushort(h0) | ((uint32_t)__bfloat16_as_ushort(h1) << 16);
        plo[i] = (uint32_t)__bfloat16_as_ushort(l0) | ((uint32_t)__bfloat16_as_ushort(l1) << 16);
    }
    size_t ob = ((size_t)b * HW + p) * 256 + cg * 32;
    uint4* dh = (uint4*)(g_Rhi + ob);
    uint4* dl = (uint4*)(g_Rlo + ob);
    #pragma unroll
    for (int i = 0; i < 4; i++) {
        dh[i] = make_uint4(phi[4*i], phi[4*i+1], phi[4*i+2], phi[4*i+3]);
        dl[i] = make_uint4(plo[4*i], plo[4*i+1], plo[4*i+2], plo[4*i+3]);
    }
}

// ---------------- step-0 replicator: R(v) unnormalized + ||v||^2 partials ----------------
__global__ void __launch_bounds__(256) k_repl0(const float* __restrict__ s0,
                                               const float* __restrict__ v) {
    int b  = blockIdx.y;
    int p  = blockIdx.x * 32 + (threadIdx.x & 31);
    int cg = threadIdx.x >> 5;
    size_t base = (size_t)b * PER_B + p;

    float sv[32], xv[32];
    float part = 0.f, nacc = 0.f;
    #pragma unroll
    for (int i = 0; i < 32; i++) {
        size_t off = base + (size_t)(cg * 32 + i) * HW;
        sv[i] = s0[off]; xv[i] = v[off];
        part += sv[i] * xv[i];
        nacc += xv[i] * xv[i];
    }
    __shared__ float red[8][32];
    __shared__ float Ssh[32];
    red[cg][threadIdx.x & 31] = part;
    __syncthreads();
    if (cg == 0) {
        float s = 0.f;
        #pragma unroll
        for (int g = 0; g < 8; g++) s += red[g][threadIdx.x];
        Ssh[threadIdx.x] = s;
    }
    __syncthreads();
    float S = Ssh[threadIdx.x & 31];

    float nr = blockReduce256(nacc);
    if (threadIdx.x == 0) g_npart[b][blockIdx.x] = nr;

    write_R(xv, sv, S, b, p, cg);
}

// ---------------- fused update + replicator + norm (k = 0..6) ----------------
__global__ void __launch_bounds__(256) k_upd_repl(const float* __restrict__ s0,
                                                  const float* __restrict__ v, int k) {
    int b  = blockIdx.y;
    int p  = blockIdx.x * 32 + (threadIdx.x & 31);
    int cg = threadIdx.x >> 5;
    size_t base = (size_t)b * PER_B + p;

    float xv[32];
    #pragma unroll
    for (int i = 0; i < 32; i++)
        xv[i] = g_w[base + (size_t)(cg * 32 + i) * HW];

    for (int j = 0; j <= k; j++) {
        const float* __restrict__ Qj = (j == 0) ? v : g_Q[j - 1];
        float cf = g_hcoef[j][b];
        #pragma unroll
        for (int i = 0; i < 32; i++)
            xv[i] -= cf * Qj[base + (size_t)(cg * 32 + i) * HW];
    }

    float* __restrict__ qn = g_Q[k];
    float sv[32];
    float nacc = 0.f, part = 0.f;
    #pragma unroll
    for (int i = 0; i < 32; i++) {
        size_t off = base + (size_t)(cg * 32 + i) * HW;
        qn[off] = xv[i];
        nacc += xv[i] * xv[i];
        sv[i] = s0[off];
        part += sv[i] * xv[i];
    }

    __shared__ float red[8][32];
    __shared__ float Ssh[32];
    red[cg][threadIdx.x & 31] = part;
    __syncthreads();
    if (cg == 0) {
        float s = 0.f;
        #pragma unroll
        for (int g = 0; g < 8; g++) s += red[g][threadIdx.x];
        Ssh[threadIdx.x] = s;
    }
    __syncthreads();
    float S = Ssh[threadIdx.x & 31];

    float nr = blockReduce256(nacc);
    if (threadIdx.x == 0) g_npart[b][blockIdx.x] = nr;

    write_R(xv, sv, S, b, p, cg);
}

// ---------------- norm finalize ----------------
__global__ void __launch_bounds__(128) k_norm_fin(int k) {
    int b = blockIdx.x, t = threadIdx.x;
    __shared__ float sh[128];
    sh[t] = g_npart[b][t]; __syncthreads();
    #pragma unroll
    for (int s = 64; s > 0; s >>= 1) { if (t < s) sh[t] += sh[t + s]; __syncthreads(); }
    if (t == 0) {
        if (k < 0) {
            float vn = sqrtf(sh[0]);
            g_vnorm[b] = vn; g_inv[0][b] = 1.f / vn;
        } else {
            float hn = sqrtf(sh[0]);
            g_H[b][k + 1][k] = hn;
            g_inv[k + 1][b]  = 1.f / (hn + EPSF);
        }
    }
}

// ---------------- dots finalize (64 partials) ----------------
__global__ void __launch_bounds__(64) k_dots_fin(int k) {
    int j = blockIdx.x, b = blockIdx.y, t = threadIdx.x;
    __shared__ float sh[64];
    sh[t] = g_dpart[j][b][t]; __syncthreads();
    #pragma unroll
    for (int s = 32; s > 0; s >>= 1) { if (t < s) sh[t] += sh[t + s]; __syncthreads(); }
    if (t == 0) {
        float h = sh[0] * g_inv[j][b];
        g_H[b][j][k]  = h;
        g_hcoef[j][b] = h * g_inv[j][b];
    }
}

// ---------------- fused GEMM + dots (pipelined, ldmatrix) ----------------
// w[b,o,p] = inv_k * sum_c W[o,c]*R[b,c,p] (3-term bf16 split), then dot partials vs Q_j.
// CTA: M=128(o) x N=128(p), K chunks of 64. 8 warps (2m x 4n), warp tile 64x32.
// smem: A hi/lo single buffer (32KB), B hi/lo double buffer (2x32KB) = 96KB.
static __device__ __forceinline__ void cp_tile(uint32_t dstbase, const __nv_bfloat16* src,
                                               int kc, int tid) {
    #pragma unroll
    for (int i = 0; i < 4; i++) {
        int x   = tid + (i << 8);           // 0..1023 16B chunks
        int row = x >> 3;
        int cb  = (x & 7) << 4;
        const char* gp = (const char*)(src + (size_t)row * 256 + kc) + cb;
        uint32_t dp = dstbase + (uint32_t)(row * 128 + (cb ^ ((row & 7) << 4)));
        CP16(dp, gp);
    }
}

__global__ void __launch_bounds__(256, 2) k_gemm_fused(const float* __restrict__ v,
                                                       int kstep, int write_w) {
    extern __shared__ __align__(128) char smem[];
    const int tid  = threadIdx.x;
    const int wid  = tid >> 5;
    const int lane = tid & 31;
    const int g    = lane >> 2;
    const int q    = lane & 3;
    const int l8   = lane & 7;
    const int g8   = lane >> 3;
    const int wm   = wid >> 2;       // 0..1
    const int wn   = wid & 3;        // 0..3
    const int p0   = blockIdx.x * 128;
    const int mt   = blockIdx.y;
    const int b    = blockIdx.z;

    uint32_t sb = smem_u32(smem);
    const uint32_t AH = sb, AL = sb + 16384;
    const uint32_t BBASE = sb + 32768;            // stage s: BBASE + s*32768 (hi), +16384 (lo)

    const __nv_bfloat16* Whi = g_Whi + (size_t)mt * 128 * 256;
    const __nv_bfloat16* Wlo = g_Wlo + (size_t)mt * 128 * 256;
    const __nv_bfloat16* Rhi = g_Rhi + ((size_t)b * HW + p0) * 256;
    const __nv_bfloat16* Rlo = g_Rlo + ((size_t)b * HW + p0) * 256;

    float acc[4][4][4];
    #pragma unroll
    for (int i = 0; i < 4; i++)
        #pragma unroll
        for (int j = 0; j < 4; j++)
            #pragma unroll
            for (int e = 0; e < 4; e++) acc[i][j][e] = 0.f;

    // prologue: B stage 0 (kc = 0)
    cp_tile(BBASE, Rhi, 0, tid);
    cp_tile(BBASE + 16384, Rlo, 0, tid);
    CP_COMMIT();

    // per-lane fragment address components
    const uint32_t aRow  = (uint32_t)(wm * 64 + (g8 & 1) * 8 + l8) * 128;
    const uint32_t swz   = (uint32_t)l8 << 4;
    const uint32_t aKsel = (uint32_t)(g8 >> 1) << 4;
    const uint32_t bKsel = (uint32_t)(g8 & 1) << 4;
    const uint32_t bRowA = (uint32_t)(wn * 32 + (g8 >> 1) * 8 + l8) * 128;   // pair j2 adds j2*16*128

    #pragma unroll
    for (int ki = 0; ki < 4; ki++) {
        const int kc = ki * 64;
        cp_tile(AH, Whi, kc, tid);
        cp_tile(AL, Wlo, kc, tid);
        CP_COMMIT();
        if (ki < 3) {
            uint32_t bn = BBASE + (uint32_t)(((ki + 1) & 1) * 32768);
            cp_tile(bn, Rhi, kc + 64, tid);
            cp_tile(bn + 16384, Rlo, kc + 64, tid);
            CP_COMMIT();
            CP_WAIT1();
        } else {
            CP_WAIT0();
        }
        __syncthreads();

        const uint32_t BH = BBASE + (uint32_t)((ki & 1) * 32768);
        const uint32_t BL = BH + 16384;

        #pragma unroll
        for (int kf = 0; kf < 4; kf++) {
            const uint32_t acol = (((uint32_t)(kf * 32)) | aKsel) ^ swz;
            const uint32_t bcol = (((uint32_t)(kf * 32)) | bKsel) ^ swz;
            uint32_t ah[4][4], al[4][4], bh[4][2], bl[4][2];
            #pragma unroll
            for (int mf = 0; mf < 4; mf++) {
                uint32_t ao = aRow + (uint32_t)(mf * 2048) + acol;
                LDSM4(ah[mf][0], ah[mf][1], ah[mf][2], ah[mf][3], AH + ao);
                LDSM4(al[mf][0], al[mf][1], al[mf][2], al[mf][3], AL + ao);
            }
            #pragma unroll
            for (int j2 = 0; j2 < 2; j2++) {
                uint32_t bo = bRowA + (uint32_t)(j2 * 16 * 128) + bcol;
                LDSM4(bh[2*j2][0], bh[2*j2][1], bh[2*j2+1][0], bh[2*j2+1][1], BH + bo);
                LDSM4(bl[2*j2][0], bl[2*j2][1], bl[2*j2+1][0], bl[2*j2+1][1], BL + bo);
            }
            #pragma unroll
            for (int mf = 0; mf < 4; mf++)
                #pragma unroll
                for (int nf = 0; nf < 4; nf++) {
                    mma_bf16(acc[mf][nf], ah[mf], bh[nf]);   // Whi*Rhi
                    mma_bf16(acc[mf][nf], al[mf], bh[nf]);   // Wlo*Rhi
                    mma_bf16(acc[mf][nf], ah[mf], bl[nf]);   // Whi*Rlo
                }
        }
        __syncthreads();
    }

    // scale by inv_k (deferred normalization of q_k)
    const float inv = g_inv[kstep][b];
    #pragma unroll
    for (int mf = 0; mf < 4; mf++)
        #pragma unroll
        for (int nf = 0; nf < 4; nf++)
            #pragma unroll
            for (int e = 0; e < 4; e++) acc[mf][nf][e] *= inv;

    if (write_w) {
        float* dst = g_w + (size_t)b * PER_B + (size_t)(mt * 128) * HW + p0;
        #pragma unroll
        for (int mf = 0; mf < 4; mf++) {
            int m = wm * 64 + mf * 16 + g;
            #pragma unroll
            for (int nf = 0; nf < 4; nf++) {
                int pp = wn * 32 + nf * 8 + q * 2;
                *(float2*)(dst + (size_t)m * HW + pp)       = make_float2(acc[mf][nf][0], acc[mf][nf][1]);
                *(float2*)(dst + (size_t)(m + 8) * HW + pp) = make_float2(acc[mf][nf][2], acc[mf][nf][3]);
            }
        }
    }

    // fused dots: partial <Q_j, w> over this CTA's 128(o) x 128(p) tile
    float* sh = (float*)smem;
    for (int j = 0; j <= kstep; j++) {
        const float* Qb = ((j == 0) ? v : g_Q[j - 1])
                        + (size_t)b * PER_B + (size_t)(mt * 128) * HW + p0;
        float d = 0.f;
        #pragma unroll
        for (int mf = 0; mf < 4; mf++) {
            int m = wm * 64 + mf * 16 + g;
            #pragma unroll
            for (int nf = 0; nf < 4; nf++) {
                int pp = wn * 32 + nf * 8 + q * 2;
                float2 a0 = *(const float2*)(Qb + (size_t)m * HW + pp);
                float2 a1 = *(const float2*)(Qb + (size_t)(m + 8) * HW + pp);
                d += acc[mf][nf][0] * a0.x + acc[mf][nf][1] * a0.y
                   + acc[mf][nf][2] * a1.x + acc[mf][nf][3] * a1.y;
            }
        }
        sh[tid] = d; __syncthreads();
        #pragma unroll
        for (int s = 128; s > 0; s >>= 1) { if (tid < s) sh[tid] += sh[tid + s]; __syncthreads(); }
        if (tid == 0) g_dpart[j][b][mt * 32 + blockIdx.x] = sh[0];
        __syncthreads();
    }
}

// ---------------- expm of 9x9 (scaling-squaring + Taylor, fp64) ----------------
__global__ void k_expm() {
    const int b = blockIdx.x;
    const int t = threadIdx.x;
    __shared__ double A[81], M[81], P[81], Pn[81];
    __shared__ int ssc;

    if (t < 81) {
        int i = t / 9, j = t % 9;
        double e = 0.0;
        if (i < 8 && j < 8) e = (double)g_H[b][i][j];
        if (i == 0 && j == 8) e = 1.0;
        A[t] = e;
    }
    __syncthreads();
    if (t == 0) {
        double nrm = 0.0;
        for (int i = 0; i < 9; i++) {
            double rs = 0.0;
            for (int j = 0; j < 9; j++) rs += fabs(A[i * 9 + j]);
            if (rs > nrm) nrm = rs;
        }
        int s = 0;
        while (nrm > 0.5 && s < 60) { nrm *= 0.5; s++; }
        ssc = s;
    }
    __syncthreads();
    const int s = ssc;
    if (t < 81) {
        A[t] = ldexp(A[t], -s);
        M[t] = ((t % 10 == 0) ? 1.0 : 0.0) + A[t];
        P[t] = A[t];
    }
    __syncthreads();
    for (int it = 2; it <= 22; it++) {
        if (t < 81) {
            int i = t / 9, j = t % 9;
            double acc = 0.0;
            #pragma unroll
            for (int kk = 0; kk < 9; kk++) acc += P[i * 9 + kk] * A[kk * 9 + j];
            Pn[t] = acc / (double)it;
        }
        __syncthreads();
        if (t < 81) { P[t] = Pn[t]; M[t] += P[t]; }
        __syncthreads();
    }
    for (int qq = 0; qq < s; qq++) {
        if (t < 81) {
            int i = t / 9, j = t % 9;
            double acc = 0.0;
            #pragma unroll
            for (int kk = 0; kk < 9; kk++) acc += M[i * 9 + kk] * M[kk * 9 + j];
            Pn[t] = acc;
        }
        __syncthreads();
        if (t < 81) M[t] = Pn[t];
        __syncthreads();
    }
    if (t < 8) {
        double coord = M[t * 9 + 8];
        g_cf[b][t] = (float)(coord * (double)g_vnorm[b] * (double)g_inv[t][b]);
    }
}

// ---------------- final combine ----------------
__global__ void __launch_bounds__(256) k_combine(const float* __restrict__ v,
                                                 float* __restrict__ out) {
    int b = blockIdx.y, blk = blockIdx.x, t = threadIdx.x;
    size_t base = (size_t)b * PER_B + (size_t)blk * 2048 + t;
    const float* qs[8];
    float cf[8];
    #pragma unroll
    for (int j = 0; j < 8; j++) { qs[j] = (j == 0) ? v : g_Q[j - 1]; cf[j] = g_cf[b][j]; }
    #pragma unroll
    for (int e = 0; e < 8; e++) {
        size_t idx = base + e * 256;
        float x = 0.f;
        #pragma unroll
        for (int j = 0; j < 8; j++) x += cf[j] * qs[j][idx];
        out[idx] = x;
    }
}

// ---------------- driver ----------------
extern "C" void kernel_launch(void* const* d_in, const int* in_sizes, int n_in,
                              void* d_out, int out_size) {
    const float* s0 = (const float*)d_in[0];
    const float* v  = (const float*)d_in[1];
    const float* Wm = (const float*)d_in[2];
    float* out = (float*)d_out;

    const int GEMM_SMEM = 98304;   // 32KB A + 2x32KB B stages
    cudaFuncSetAttribute(k_gemm_fused, cudaFuncAttributeMaxDynamicSharedMemorySize, GEMM_SMEM);

    dim3 gP(HW / 32, Bb);            // update/replicator grids
    dim3 gGemm(HW / 128, 2, Bb);     // 32 p-tiles x 2 m-tiles x 8 batches
    dim3 gEl(512, Bb);

    k_splitW<<<Cc * Cc / 256, 256>>>(Wm);
    k_repl0<<<gP, 256>>>(s0, v);
    k_norm_fin<<<Bb, 128>>>(-1);

    for (int k = 0; k < 8; k++) {
        k_gemm_fused<<<gGemm, 256, GEMM_SMEM>>>(v, k, (k < 7) ? 1 : 0);
        k_dots_fin<<<dim3(k + 1, Bb), 64>>>(k);
        if (k < 7) {
            k_upd_repl<<<gP, 256>>>(s0, v, k);
            k_norm_fin<<<Bb, 128>>>(k);
        }
    }

    k_expm<<<Bb, 128>>>();
    k_combine<<<gEl, 256>>>(v, out);
}

// round 6
// speedup vs baseline: 1.2735x; 1.0394x over previous
#include <cuda_runtime.h>
#include <cuda_bf16.h>
#include <math.h>
#include <stdint.h>

#define Bb    8
#define Cc    256
#define HW    4096
#define PER_B (Cc * HW)          // 2^20
#define EPSF  1e-12f

// ---------------- device scratch ----------------
__device__ float g_Q[7][Bb * PER_B];   // unnormalized Krylov vectors, slots 1..7 (slot 0 = input v)
__device__ float g_w[Bb * PER_B];      // GEMM output (scaled by inv_k)
__device__ __nv_bfloat16 g_Rhi[Bb * PER_B];  // replicator out (UNNORMALIZED), transposed [b][p][c], hi
__device__ __nv_bfloat16 g_Rlo[Bb * PER_B];  // lo residual
__device__ __nv_bfloat16 g_Whi[Cc * Cc];
__device__ __nv_bfloat16 g_Wlo[Cc * Cc];
__device__ float g_dpart[8][Bb][64];   // raw dot partials [j][b][mt*32+pblock]
__device__ float g_npart[Bb][128];     // norm partials
__device__ float g_H[Bb][8][8];
__device__ float g_inv[8][Bb];
__device__ float g_vnorm[Bb];
__device__ float g_cf[Bb][8];

// ---------------- PTX helpers ----------------
static __device__ __forceinline__ uint32_t smem_u32(const void* p) {
    uint32_t a;
    asm("{ .reg .u64 t; cvta.to.shared.u64 t, %1; cvt.u32.u64 %0, t; }" : "=r"(a) : "l"(p));
    return a;
}
#define CP16(dst, src) \
    asm volatile("cp.async.cg.shared.global [%0], [%1], 16;" :: "r"(dst), "l"(src))
#define CP_COMMIT() asm volatile("cp.async.commit_group;" ::: "memory")
#define CP_WAIT0()  asm volatile("cp.async.wait_group 0;" ::: "memory")
#define LDSM4(r0, r1, r2, r3, addr) \
    asm volatile("ldmatrix.sync.aligned.m8n8.x4.shared.b16 {%0,%1,%2,%3}, [%4];" \
        : "=r"(r0), "=r"(r1), "=r"(r2), "=r"(r3) : "r"(addr))

static __device__ __forceinline__ void mma_bf16(float* c, const uint32_t* a, const uint32_t* b) {
    asm volatile("mma.sync.aligned.m16n8k16.row.col.f32.bf16.bf16.f32 "
        "{%0,%1,%2,%3}, {%4,%5,%6,%7}, {%8,%9}, {%0,%1,%2,%3};"
        : "+f"(c[0]), "+f"(c[1]), "+f"(c[2]), "+f"(c[3])
        : "r"(a[0]), "r"(a[1]), "r"(a[2]), "r"(a[3]), "r"(b[0]), "r"(b[1]));
}

static __device__ __forceinline__ float warpReduce(float v) {
    #pragma unroll
    for (int off = 16; off > 0; off >>= 1) v += __shfl_xor_sync(0xFFFFFFFFu, v, off);
    return v;
}

// ---------------- W split to bf16 hi/lo ----------------
__global__ void __launch_bounds__(256) k_splitW(const float* __restrict__ Wm) {
    int i = blockIdx.x * 256 + threadIdx.x;
    float x = Wm[i];
    __nv_bfloat16 h = __float2bfloat16(x);
    g_Whi[i] = h;
    g_Wlo[i] = __float2bfloat16(x - __bfloat162float(h));
}

// ---------------- write transposed bf16-split R from 16 per-thread values ----------------
static __device__ __forceinline__ void write_R16(const float* xv, const float* sv, float S,
                                                 int b, int p, int cg) {
    uint32_t phi[8], plo[8];
    #pragma unroll
    for (int i = 0; i < 8; i++) {
        float x0 = sv[2*i]   * (xv[2*i]   - S);
        float x1 = sv[2*i+1] * (xv[2*i+1] - S);
        __nv_bfloat16 h0 = __float2bfloat16(x0);
        __nv_bfloat16 h1 = __float2bfloat16(x1);
        __nv_bfloat16 l0 = __float2bfloat16(x0 - __bfloat162float(h0));
        __nv_bfloat16 l1 = __float2bfloat16(x1 - __bfloat162float(h1));
        phi[i] = (uint32_t)__bfloat16_as_ushort(h0) | ((uint32_t)__bfloat16_as_ushort(h1) << 16);
        plo[i] = (uint32_t)__bfloat16_as_ushort(l0) | ((uint32_t)__bfloat16_as_ushort(l1) << 16);
    }
    size_t ob = ((size_t)b * HW + p) * 256 + cg * 16;
    uint4* dh = (uint4*)(g_Rhi + ob);
    uint4* dl = (uint4*)(g_Rlo + ob);
    #pragma unroll
    for (int i = 0; i < 2; i++) {
        dh[i] = make_uint4(phi[4*i], phi[4*i+1], phi[4*i+2], phi[4*i+3]);
        dl[i] = make_uint4(plo[4*i], plo[4*i+1], plo[4*i+2], plo[4*i+3]);
    }
}

// ---------------- step-0 replicator: R(v) unnormalized + ||v||^2 partials ----------------
__global__ void __launch_bounds__(512) k_repl0(const float* __restrict__ s0,
                                               const float* __restrict__ v) {
    const int lane = threadIdx.x & 31, cg = threadIdx.x >> 5;  // cg 0..15
    const int b = blockIdx.y;
    const int p = blockIdx.x * 32 + lane;
    size_t base = (size_t)b * PER_B + p;

    float sv[16], xv[16];
    float part = 0.f, nacc = 0.f;
    #pragma unroll
    for (int i = 0; i < 16; i++) {
        size_t off = base + (size_t)(cg * 16 + i) * HW;
        sv[i] = s0[off]; xv[i] = v[off];
        part += sv[i] * xv[i];
        nacc += xv[i] * xv[i];
    }
    __shared__ float red[16][32], Ssh[32], nsh[16];
    float nw = warpReduce(nacc);
    red[cg][lane] = part;
    if (lane == 0) nsh[cg] = nw;
    __syncthreads();
    if (cg == 0) {
        float s = 0.f;
        #pragma unroll
        for (int g2 = 0; g2 < 16; g2++) s += red[g2][lane];
        Ssh[lane] = s;
    }
    if (cg == 1 && lane == 0) {
        float s = 0.f;
        #pragma unroll
        for (int g2 = 0; g2 < 16; g2++) s += nsh[g2];
        g_npart[b][blockIdx.x] = s;
    }
    __syncthreads();
    float S = Ssh[lane];
    write_R16(xv, sv, S, b, p, cg);
}

// ---------------- vnorm finalize ----------------
__global__ void __launch_bounds__(128) k_vnorm_fin() {
    int b = blockIdx.x, t = threadIdx.x;
    __shared__ float sh[128];
    sh[t] = g_npart[b][t]; __syncthreads();
    #pragma unroll
    for (int s = 64; s > 0; s >>= 1) { if (t < s) sh[t] += sh[t + s]; __syncthreads(); }
    if (t == 0) { float vn = sqrtf(sh[0]); g_vnorm[b] = vn; g_inv[0][b] = 1.f / vn; }
}

// ---------------- fused update + replicator + dots_fin + norm (k = 0..6) ----------------
__global__ void __launch_bounds__(512) k_upd_repl(const float* __restrict__ s0,
                                                  const float* __restrict__ v, int k) {
    const int lane = threadIdx.x & 31, cg = threadIdx.x >> 5;  // cg = warp id 0..15
    const int b = blockIdx.y;
    const int p = blockIdx.x * 32 + lane;
    size_t base = (size_t)b * PER_B + p;

    // inline dots finalize: warp j (j<=k) reduces 64 partials -> hcoef
    __shared__ float hc[8];
    if (cg <= k) {
        float dv = g_dpart[cg][b][lane] + g_dpart[cg][b][lane + 32];
        dv = warpReduce(dv);
        if (lane == 0) {
            float invj = g_inv[cg][b];
            float h = dv * invj;
            hc[cg] = h * invj;
            if (blockIdx.x == 0) g_H[b][cg][k] = h;
        }
    }
    __syncthreads();

    float xv[16];
    #pragma unroll
    for (int i = 0; i < 16; i++)
        xv[i] = g_w[base + (size_t)(cg * 16 + i) * HW];

    for (int j = 0; j <= k; j++) {
        const float* __restrict__ Qj = (j == 0) ? v : g_Q[j - 1];
        float cf = hc[j];
        #pragma unroll
        for (int i = 0; i < 16; i++)
            xv[i] -= cf * Qj[base + (size_t)(cg * 16 + i) * HW];
    }

    float* __restrict__ qn = g_Q[k];
    float sv[16];
    float nacc = 0.f, part = 0.f;
    #pragma unroll
    for (int i = 0; i < 16; i++) {
        size_t off = base + (size_t)(cg * 16 + i) * HW;
        qn[off] = xv[i];
        nacc += xv[i] * xv[i];
        sv[i] = s0[off];
        part += sv[i] * xv[i];
    }

    __shared__ float red[16][32], Ssh[32], nsh[16];
    float nw = warpReduce(nacc);
    red[cg][lane] = part;
    if (lane == 0) nsh[cg] = nw;
    __syncthreads();
    if (cg == 0) {
        float s = 0.f;
        #pragma unroll
        for (int g2 = 0; g2 < 16; g2++) s += red[g2][lane];
        Ssh[lane] = s;
    }
    if (cg == 1 && lane == 0) {
        float s = 0.f;
        #pragma unroll
        for (int g2 = 0; g2 < 16; g2++) s += nsh[g2];
        g_npart[b][blockIdx.x] = s;
    }
    __syncthreads();
    float S = Ssh[lane];
    write_R16(xv, sv, S, b, p, cg);
}

// ---------------- fused GEMM + dots (1-sync/chunk pipeline, inline norm finalize) ----------------
// w[b,o,p] = inv_k * sum_c W[o,c]*R[b,c,p] (3-term bf16 split), then raw dot partials vs Q_j.
// CTA: M=128(o) x N=128(p). 8 K-chunks of 32, A+B double-buffered (2 x 32KB smem).
// Tile layout: 128 rows x 64B, swizzle: cb ^ (((row>>1)&3)<<4).
static __device__ __forceinline__ void cp_tile32(uint32_t dstbase, const __nv_bfloat16* src,
                                                 int kc, int tid) {
    #pragma unroll
    for (int i = 0; i < 2; i++) {
        int x   = tid + (i << 8);     // 0..511 16B chunks
        int row = x >> 2;             // 0..127
        int cb  = (x & 3) << 4;       // 0,16,32,48
        const char* gp = (const char*)(src + (size_t)row * 256 + kc) + cb;
        uint32_t dp = dstbase + (uint32_t)(row * 64 + (cb ^ (((row >> 1) & 3) << 4)));
        CP16(dp, gp);
    }
}

__global__ void __launch_bounds__(256, 2) k_gemm_fused(const float* __restrict__ v,
                                                       int kstep, int write_w) {
    extern __shared__ __align__(128) char smem[];
    const int tid  = threadIdx.x;
    const int wid  = tid >> 5;
    const int lane = tid & 31;
    const int g    = lane >> 2;
    const int q    = lane & 3;
    const int l8   = lane & 7;
    const int g8   = lane >> 3;
    const int wm   = wid >> 2;       // 0..1
    const int wn   = wid & 3;        // 0..3
    const int p0   = blockIdx.x * 128;
    const int mt   = blockIdx.y;
    const int b    = blockIdx.z;

    uint32_t sb = smem_u32(smem);

    const __nv_bfloat16* Whi = g_Whi + (size_t)mt * 128 * 256;
    const __nv_bfloat16* Wlo = g_Wlo + (size_t)mt * 128 * 256;
    const __nv_bfloat16* Rhi = g_Rhi + ((size_t)b * HW + p0) * 256;
    const __nv_bfloat16* Rlo = g_Rlo + ((size_t)b * HW + p0) * 256;

    // prologue: chunk 0 into stage 0
    cp_tile32(sb,         Whi, 0, tid);
    cp_tile32(sb + 8192,  Wlo, 0, tid);
    cp_tile32(sb + 16384, Rhi, 0, tid);
    cp_tile32(sb + 24576, Rlo, 0, tid);
    CP_COMMIT();

    // inline norm finalize -> inv_k (overlaps chunk-0 load)
    __shared__ float invsh;
    __shared__ float rsh[4];
    if (kstep == 0) {
        if (tid == 0) invsh = g_inv[0][b];
    } else {
        if (tid < 128) {
            float val = warpReduce(g_npart[b][tid]);
            if (lane == 0) rsh[wid] = val;
        }
        __syncthreads();
        if (tid == 0) {
            float hn = sqrtf(rsh[0] + rsh[1] + rsh[2] + rsh[3]);
            float iv = 1.f / (hn + EPSF);
            invsh = iv;
            if (blockIdx.x == 0 && blockIdx.y == 0) {
                g_inv[kstep][b] = iv;
                g_H[b][kstep][kstep - 1] = hn;
            }
        }
    }

    float acc[4][4][4];
    #pragma unroll
    for (int i = 0; i < 4; i++)
        #pragma unroll
        for (int j = 0; j < 4; j++)
            #pragma unroll
            for (int e = 0; e < 4; e++) acc[i][j][e] = 0.f;

    const uint32_t aR0 = (uint32_t)(wm * 64 + (g8 & 1) * 8 + l8);
    const uint32_t bR0 = (uint32_t)(wn * 32 + (g8 >> 1) * 8 + l8);
    const uint32_t aK  = (uint32_t)(g8 >> 1) << 4;
    const uint32_t bK  = (uint32_t)(g8 & 1) << 4;

    #pragma unroll
    for (int ci = 0; ci < 8; ci++) {
        CP_WAIT0();
        __syncthreads();
        if (ci < 7) {
            uint32_t st = sb + (uint32_t)(((ci + 1) & 1) * 32768);
            int kc = (ci + 1) * 32;
            cp_tile32(st,         Whi, kc, tid);
            cp_tile32(st + 8192,  Wlo, kc, tid);
            cp_tile32(st + 16384, Rhi, kc, tid);
            cp_tile32(st + 24576, Rlo, kc, tid);
            CP_COMMIT();
        }
        const uint32_t ST = sb + (uint32_t)((ci & 1) * 32768);
        const uint32_t AHs = ST, ALs = ST + 8192, BHs = ST + 16384, BLs = ST + 24576;

        #pragma unroll
        for (int kf = 0; kf < 2; kf++) {
            const uint32_t cbA = (uint32_t)(kf * 32) + aK;
            const uint32_t cbB = (uint32_t)(kf * 32) + bK;
            uint32_t ah[4][4], al[4][4], bh[4][2], bl[4][2];
            #pragma unroll
            for (int mf = 0; mf < 4; mf++) {
                uint32_t r  = aR0 + (uint32_t)(mf * 16);
                uint32_t ao = r * 64 + (cbA ^ (((r >> 1) & 3) << 4));
                LDSM4(ah[mf][0], ah[mf][1], ah[mf][2], ah[mf][3], AHs + ao);
                LDSM4(al[mf][0], al[mf][1], al[mf][2], al[mf][3], ALs + ao);
            }
            #pragma unroll
            for (int j2 = 0; j2 < 2; j2++) {
                uint32_t r  = bR0 + (uint32_t)(j2 * 16);
                uint32_t bo = r * 64 + (cbB ^ (((r >> 1) & 3) << 4));
                LDSM4(bh[2*j2][0], bh[2*j2][1], bh[2*j2+1][0], bh[2*j2+1][1], BHs + bo);
                LDSM4(bl[2*j2][0], bl[2*j2][1], bl[2*j2+1][0], bl[2*j2+1][1], BLs + bo);
            }
            #pragma unroll
            for (int mf = 0; mf < 4; mf++)
                #pragma unroll
                for (int nf = 0; nf < 4; nf++) {
                    mma_bf16(acc[mf][nf], ah[mf], bh[nf]);   // Whi*Rhi
                    mma_bf16(acc[mf][nf], al[mf], bh[nf]);   // Wlo*Rhi
                    mma_bf16(acc[mf][nf], ah[mf], bl[nf]);   // Whi*Rlo
                }
        }
    }

    // scale by inv_k (deferred normalization of q_k)
    const float inv = invsh;
    #pragma unroll
    for (int mf = 0; mf < 4; mf++)
        #pragma unroll
        for (int nf = 0; nf < 4; nf++)
            #pragma unroll
            for (int e = 0; e < 4; e++) acc[mf][nf][e] *= inv;

    if (write_w) {
        float* dst = g_w + (size_t)b * PER_B + (size_t)(mt * 128) * HW + p0;
        #pragma unroll
        for (int mf = 0; mf < 4; mf++) {
            int m = wm * 64 + mf * 16 + g;
            #pragma unroll
            for (int nf = 0; nf < 4; nf++) {
                int pp = wn * 32 + nf * 8 + q * 2;
                *(float2*)(dst + (size_t)m * HW + pp)       = make_float2(acc[mf][nf][0], acc[mf][nf][1]);
                *(float2*)(dst + (size_t)(m + 8) * HW + pp) = make_float2(acc[mf][nf][2], acc[mf][nf][3]);
            }
        }
    }

    // fused dots: raw partial <Q_j, w> over this CTA's 128x128 tile
    __shared__ float dsh[8][8];
    for (int j = 0; j <= kstep; j++) {
        const float* Qb = ((j == 0) ? v : g_Q[j - 1])
                        + (size_t)b * PER_B + (size_t)(mt * 128) * HW + p0;
        float d = 0.f;
        #pragma unroll
        for (int mf = 0; mf < 4; mf++) {
            int m = wm * 64 + mf * 16 + g;
            #pragma unroll
            for (int nf = 0; nf < 4; nf++) {
                int pp = wn * 32 + nf * 8 + q * 2;
                float2 a0 = *(const float2*)(Qb + (size_t)m * HW + pp);
                float2 a1 = *(const float2*)(Qb + (size_t)(m + 8) * HW + pp);
                d += acc[mf][nf][0] * a0.x + acc[mf][nf][1] * a0.y
                   + acc[mf][nf][2] * a1.x + acc[mf][nf][3] * a1.y;
            }
        }
        d = warpReduce(d);
        if (lane == 0) dsh[j][wid] = d;
    }
    __syncthreads();
    if (tid < 64) {
        int j = tid >> 3, w8 = tid & 7;
        float val = (j <= kstep) ? dsh[j][w8] : 0.f;
        #pragma unroll
        for (int off = 4; off > 0; off >>= 1) val += __shfl_xor_sync(0xFFFFFFFFu, val, off);
        if (w8 == 0 && j <= kstep) g_dpart[j][b][mt * 32 + blockIdx.x] = val;
    }
}

// ---------------- expm of 9x9 (scaling-squaring + Taylor, fp64) + H col 7 finalize ----------------
__global__ void k_expm() {
    const int b = blockIdx.x;
    const int t = threadIdx.x;
    __shared__ double A[81], M[81], P[81], Pn[81];
    __shared__ float Hc7[8];
    __shared__ int ssc;

    if (t < 8) {
        float dv = 0.f;
        for (int i2 = 0; i2 < 64; i2++) dv += g_dpart[t][b][i2];
        Hc7[t] = dv * g_inv[t][b];
    }
    __syncthreads();

    if (t < 81) {
        int i = t / 9, j = t % 9;
        double e = 0.0;
        if (i < 8 && j < 8) e = (j == 7) ? (double)Hc7[i] : (double)g_H[b][i][j];
        if (i == 0 && j == 8) e = 1.0;
        A[t] = e;
    }
    __syncthreads();
    if (t == 0) {
        double nrm = 0.0;
        for (int i = 0; i < 9; i++) {
            double rs = 0.0;
            for (int j = 0; j < 9; j++) rs += fabs(A[i * 9 + j]);
            if (rs > nrm) nrm = rs;
        }
        int s = 0;
        while (nrm > 0.5 && s < 60) { nrm *= 0.5; s++; }
        ssc = s;
    }
    __syncthreads();
    const int s = ssc;
    if (t < 81) {
        A[t] = ldexp(A[t], -s);
        M[t] = ((t % 10 == 0) ? 1.0 : 0.0) + A[t];
        P[t] = A[t];
    }
    __syncthreads();
    for (int it = 2; it <= 22; it++) {
        if (t < 81) {
            int i = t / 9, j = t % 9;
            double acc = 0.0;
            #pragma unroll
            for (int kk = 0; kk < 9; kk++) acc += P[i * 9 + kk] * A[kk * 9 + j];
            Pn[t] = acc / (double)it;
        }
        __syncthreads();
        if (t < 81) { P[t] = Pn[t]; M[t] += P[t]; }
        __syncthreads();
    }
    for (int qq = 0; qq < s; qq++) {
        if (t < 81) {
            int i = t / 9, j = t % 9;
            double acc = 0.0;
            #pragma unroll
            for (int kk = 0; kk < 9; kk++) acc += M[i * 9 + kk] * M[kk * 9 + j];
            Pn[t] = acc;
        }
        __syncthreads();
        if (t < 81) M[t] = Pn[t];
        __syncthreads();
    }
    if (t < 8) {
        double coord = M[t * 9 + 8];
        g_cf[b][t] = (float)(coord * (double)g_vnorm[b] * (double)g_inv[t][b]);
    }
}

// ---------------- final combine ----------------
__global__ void __launch_bounds__(256) k_combine(const float* __restrict__ v,
                                                 float* __restrict__ out) {
    int b = blockIdx.y, blk = blockIdx.x, t = threadIdx.x;
    size_t base = (size_t)b * PER_B + (size_t)blk * 2048 + t;
    const float* qs[8];
    float cf[8];
    #pragma unroll
    for (int j = 0; j < 8; j++) { qs[j] = (j == 0) ? v : g_Q[j - 1]; cf[j] = g_cf[b][j]; }
    #pragma unroll
    for (int e = 0; e < 8; e++) {
        size_t idx = base + e * 256;
        float x = 0.f;
        #pragma unroll
        for (int j = 0; j < 8; j++) x += cf[j] * qs[j][idx];
        out[idx] = x;
    }
}

// ---------------- driver ----------------
extern "C" void kernel_launch(void* const* d_in, const int* in_sizes, int n_in,
                              void* d_out, int out_size) {
    const float* s0 = (const float*)d_in[0];
    const float* v  = (const float*)d_in[1];
    const float* Wm = (const float*)d_in[2];
    float* out = (float*)d_out;

    const int GEMM_SMEM = 65536;   // 2 stages x 32KB
    cudaFuncSetAttribute(k_gemm_fused, cudaFuncAttributeMaxDynamicSharedMemorySize, GEMM_SMEM);

    dim3 gP(HW / 32, Bb);            // 128 p-blocks x 8 batches (512-thread kernels)
    dim3 gGemm(HW / 128, 2, Bb);     // 32 p-tiles x 2 m-tiles x 8 batches
    dim3 gEl(512, Bb);

    k_splitW<<<Cc * Cc / 256, 256>>>(Wm);
    k_repl0<<<gP, 512>>>(s0, v);
    k_vnorm_fin<<<Bb, 128>>>();

    for (int k = 0; k < 8; k++) {
        k_gemm_fused<<<gGemm, 256, GEMM_SMEM>>>(v, k, (k < 7) ? 1 : 0);
        if (k < 7) k_upd_repl<<<gP, 512>>>(s0, v, k);
    }

    k_expm<<<Bb, 128>>>();
    k_combine<<<gEl, 256>>>(v, out);
}